// round 9
// baseline (speedup 1.0000x reference)
#include <cuda_runtime.h>
#include <cstdint>

// MultiDirectionPattern: masked 8-direction pooling + saliency gather.
// 64-thread CTAs, 32 rows per CTA staged by ONE 6272B cp.async.bulk.
// Two lanes per row: warp0 lane r -> dirs 0-3 of row r, warp1 lane r ->
// dirs 4-7 of row r (each warp reads 32 distinct stride-49 rows: LDS
// conflict-free). Mask verify is split across all 64 threads (2xLDG.128 each)
// and merged with one __syncthreads. Sal gather reads s directly.

static constexpr int HW    = 49;     // 7*7
static constexpr int TPB   = 64;
static constexpr int SROW  = 3136;   // 56*56
static constexpr int CROWS = 32;     // rows per CTA
static constexpr int CF    = CROWS * HW;   // 1568 floats
static constexpr int CBYTES = CF * 4;      // 6272 bytes

// Natural-packed 392-bit bitmap: bit (p*49+k) set <=> feat_mask[p][k] != 0.
__constant__ uint32_t c_bits[13] = {
    0x0F000000u, 0x00010307u, 0xC3830200u, 0x04000003u, 0x0000F1C3u,
    0x20C38F00u, 0x1E1C1810u, 0xE1E00000u, 0x00002060u, 0x41871E00u,
    0x20000000u, 0x00078E18u, 0x00000000u
};

__device__ __forceinline__ void cp16(uint32_t dst, const void* src) {
    asm volatile("cp.async.cg.shared.global [%0], [%1], 16;\n" :: "r"(dst), "l"(src));
}
__device__ __forceinline__ void cp4(uint32_t dst, const void* src) {
    asm volatile("cp.async.ca.shared.global [%0], [%1], 4;\n" :: "r"(dst), "l"(src));
}
__device__ __forceinline__ void cp_commit() {
    asm volatile("cp.async.commit_group;\n" ::: "memory");
}
__device__ __forceinline__ void cp_wait_all() {
    asm volatile("cp.async.wait_group 0;\n" ::: "memory");
}
__device__ __forceinline__ void mbar_init(uint32_t mbar, uint32_t cnt) {
    asm volatile("mbarrier.init.shared.b64 [%0], %1;\n" :: "r"(mbar), "r"(cnt) : "memory");
}
__device__ __forceinline__ void fence_async() {
    asm volatile("fence.proxy.async.shared::cta;\n" ::: "memory");
}
__device__ __forceinline__ void mbar_expect_tx(uint32_t mbar, uint32_t bytes) {
    asm volatile("mbarrier.arrive.expect_tx.shared.b64 _, [%0], %1;\n"
                 :: "r"(mbar), "r"(bytes) : "memory");
}
__device__ __forceinline__ void cp_bulk(uint32_t dst, const void* src,
                                        uint32_t bytes, uint32_t mbar) {
    asm volatile("cp.async.bulk.shared::cta.global.mbarrier::complete_tx::bytes "
                 "[%0], [%1], %2, [%3];\n"
                 :: "r"(dst), "l"(src), "r"(bytes), "r"(mbar) : "memory");
}
__device__ __forceinline__ void mbar_wait(uint32_t mbar, uint32_t parity) {
    uint32_t done;
    asm volatile(
        "{\n\t.reg .pred p;\n\t"
        "mbarrier.try_wait.parity.acquire.cta.shared::cta.b64 p, [%1], %2;\n\t"
        "selp.b32 %0, 1, 0, p;\n\t}"
        : "=r"(done) : "r"(mbar), "r"(parity) : "memory");
    if (!done) {
        asm volatile(
            "{\n\t.reg .pred P1;\n\t"
            "WL_%=:\n\t"
            "mbarrier.try_wait.parity.acquire.cta.shared::cta.b64 P1, [%0], %1, 0x989680;\n\t"
            "@P1 bra.uni WD_%=;\n\t"
            "bra.uni WL_%=;\n\t"
            "WD_%=:\n\t}"
            :: "r"(mbar), "r"(parity) : "memory");
    }
}

__global__ __launch_bounds__(TPB, 24) void fused_kernel(
    const float* __restrict__ x,
    const float* __restrict__ s,
    const float* __restrict__ fm,
    const int*   __restrict__ sal_idx,
    float*       __restrict__ out,
    int rows,             // B*C
    int B,                // batch (sal blocks are blk < B)
    int N,                // saliency points per direction
    long long feat_elems  // rows*8
) {
    __shared__ __align__(16) float sm[CF];
    __shared__ __align__(8) unsigned long long smbar;
    __shared__ int smbad[2];
    const int blk = blockIdx.x;
    const int t   = threadIdx.x;

    if (blk >= B) {
        // ============ feat tile: 32 rows, one bulk copy ============
        const uint32_t sbase = (uint32_t)__cvta_generic_to_shared(sm);
        const uint32_t mbar  = (uint32_t)__cvta_generic_to_shared(&smbar);
        const long long row0 = (long long)(blk - B) * CROWS;
        long long rem = rows - row0;
        const int rh = rem < CROWS ? (int)rem : CROWS;
        const float* xc = x + row0 * HW;         // row0 mult of 32 -> 16B aligned
        const bool full = (rh == CROWS);

        if (full) {
            if (t == 0) {
                mbar_init(mbar, 1);
                fence_async();
                mbar_expect_tx(mbar, CBYTES);
                cp_bulk(sbase, xc, CBYTES, mbar);
            }
        } else {
            const int total = rh * HW;
            const int n4 = total >> 2;
            const float4* xc4 = (const float4*)xc;
            for (int i = t; i < n4; i += TPB) cp16(sbase + i * 16, xc4 + i);
            for (int i = 4 * n4 + t; i < total; i += TPB) cp4(sbase + i * 4, xc + i);
            cp_commit();
        }

        // verify mask while copy flies: 2x LDG.128 + 8 bit checks per thread
        int mybad = 0;
        const float4* fm4 = (const float4*)fm;   // 392 floats = 98 float4
        #pragma unroll
        for (int j = 0; j < 2; ++j) {
            int q = t + j * TPB;
            if (q < 98) {
                float4 v = __ldg(fm4 + q);
                int i = q * 4;
                float e0 = ((c_bits[(i    ) >> 5] >> ((i    ) & 31)) & 1u) ? 1.0f : 0.0f;
                float e1 = ((c_bits[(i + 1) >> 5] >> ((i + 1) & 31)) & 1u) ? 1.0f : 0.0f;
                float e2 = ((c_bits[(i + 2) >> 5] >> ((i + 2) & 31)) & 1u) ? 1.0f : 0.0f;
                float e3 = ((c_bits[(i + 3) >> 5] >> ((i + 3) & 31)) & 1u) ? 1.0f : 0.0f;
                if (v.x != e0 || v.y != e1 || v.z != e2 || v.w != e3) mybad = 1;
            }
        }
        const int w = t >> 5;
        if ((t & 31) == 0) smbad[w] = 0;
        int wbad = __any_sync(0xffffffffu, mybad);
        if ((t & 31) == 0) smbad[w] = wbad;

        if (!full) cp_wait_all();
        __syncthreads();                          // smbad + cp.async data + mbar init
        if (full) mbar_wait(mbar, 0);             // acquire: bulk data visible
        const bool fb = (smbad[0] | smbad[1]) != 0;

        // two lanes per row: warp0 -> dirs 0-3, warp1 -> dirs 4-7
        const int r = t & 31;
        if (r < rh) {
            const float* xr = sm + r * HW;        // 32 distinct rows per warp: conflict-free
            float o0, o1, o2, o3;
            const float x24 = xr[24];
            if (!fb) {
                const float wgt = 0.1f;
                if (w == 0) {
                    float R0 = xr[25] + xr[26] + xr[27];
                    float R1 = xr[32] + xr[40] + xr[48];
                    float R2 = xr[31] + xr[38] + xr[45];
                    float R3 = xr[30] + xr[36] + xr[42];
                    float R4 = xr[21] + xr[22] + xr[23];
                    float I0 = xr[33] + xr[34] + xr[41];
                    float I1 = xr[39] + xr[46] + xr[47];
                    float I2 = xr[37] + xr[43] + xr[44];
                    float I3 = xr[28] + xr[29] + xr[35];
                    o0 = (R0 + I0 + R1 + x24) * wgt;
                    o1 = (R1 + I1 + R2 + x24) * wgt;
                    o2 = (R2 + I2 + R3 + x24) * wgt;
                    o3 = (R3 + I3 + R4 + x24) * wgt;
                } else {
                    float R4 = xr[21] + xr[22] + xr[23];
                    float R5 = xr[ 0] + xr[ 8] + xr[16];
                    float R6 = xr[ 3] + xr[10] + xr[17];
                    float R7 = xr[ 6] + xr[12] + xr[18];
                    float R0 = xr[25] + xr[26] + xr[27];
                    float I4 = xr[ 7] + xr[14] + xr[15];
                    float I5 = xr[ 1] + xr[ 2] + xr[ 9];
                    float I6 = xr[ 4] + xr[ 5] + xr[11];
                    float I7 = xr[13] + xr[19] + xr[20];
                    o0 = (R4 + I4 + R5 + x24) * wgt;
                    o1 = (R5 + I5 + R6 + x24) * wgt;
                    o2 = (R6 + I6 + R7 + x24) * wgt;
                    o3 = (R7 + I7 + R0 + x24) * wgt;
                }
            } else {
                // generic dense fallback (rare): mask from gmem (cached)
                const int p0 = w * 4;
                float a[4] = {0, 0, 0, 0};
                float c[4] = {0, 0, 0, 0};
                for (int k = 0; k < HW; ++k) {
                    float xv = xr[k];
                    #pragma unroll
                    for (int q = 0; q < 4; ++q) {
                        float m = __ldg(fm + (p0 + q) * HW + k);
                        a[q] += xv * m;
                        c[q] += (m != 0.0f) ? 1.0f : 0.0f;
                    }
                }
                o0 = a[0] / c[0]; o1 = a[1] / c[1];
                o2 = a[2] / c[2]; o3 = a[3] / c[3];
            }
            float* op = out + (row0 + r) * 8 + w * 4;
            *(float4*)op = make_float4(o0, o1, o2, o3);
        }
    } else {
        // ============ sal gather: direct (no smem), one block per batch ====
        const int b = blk;
        const float* sb = s + (long long)b * SROW;
        float* ob = out + feat_elems + (long long)b * (8LL * N);
        for (int n = t; n < N; n += TPB) {
            float v[8];
            #pragma unroll
            for (int p = 0; p < 8; ++p)
                v[p] = __ldg(sb + __ldg(sal_idx + p * N + n));
            float4* op = (float4*)(ob + n * 8);
            op[0] = make_float4(v[0], v[1], v[2], v[3]);
            op[1] = make_float4(v[4], v[5], v[6], v[7]);
        }
    }
}

extern "C" void kernel_launch(void* const* d_in, const int* in_sizes, int n_in,
                              void* d_out, int out_size) {
    const float* x       = (const float*)d_in[0];
    const float* s       = (const float*)d_in[1];
    const float* fm      = (const float*)d_in[2];
    const int*   sal_idx = (const int*)d_in[3];
    float*       out     = (float*)d_out;

    const int rows = in_sizes[0] / HW;    // B*C
    const int B    = in_sizes[1] / SROW;  // batch
    const int N    = in_sizes[3] / 8;     // points per direction
    const int nfb  = (rows + CROWS - 1) / CROWS;
    const long long feat_elems = (long long)rows * 8;

    fused_kernel<<<B + nfb, TPB>>>(x, s, fm, sal_idx, out, rows, B, N, feat_elems);
}